// round 8
// baseline (speedup 1.0000x reference)
#include <cuda_runtime.h>
#include <math.h>

// Problem constants
#define HH 768
#define WW 768
#define NIMG 32
#define HWI (768 * 768)
#define HWLL (768LL * 768LL)

// Tile: 128 cols x 64 rows per block; block (32,8); thread = 4 cols x 8 rows
#define TW 128
#define TH 64
#define SW3 132              // TW + 4 (2-col halo both sides; output j at smem col j+2)
#define SH2 68               // TH + 4
#define BLOCKS_X (WW / TW)   // 6
#define BLOCKS_Y (HH / TH)   // 12
#define BPI (BLOCKS_X * BLOCKS_Y)  // 72 blocks per image

#define MIN_WEIGHT 0.1f

__device__ float g_part[NIMG * BPI];   // fully rewritten every run

__device__ __forceinline__ float tanh_a(float x) {
    float r;
    asm("tanh.approx.f32 %0, %1;" : "=f"(r) : "f"(x));
    return r;
}
__device__ __forceinline__ float sigm(float x) {
    return fmaf(0.5f, tanh_a(0.5f * x), 0.5f);
}

// 5-wide horizontal sums for 4 outputs from TWO aligned float4 LDS
// (outputs j=4t..4t+3 need smem cols 4t..4t+7 thanks to the +2 halo shift;
//  row stride 132 floats = 528 B = 33*16 -> sp[r][j4] is 16B aligned)
#define HSQ(r, hs, hq)                                                         \
{                                                                              \
    const float4 L = *reinterpret_cast<const float4*>(&sp[(r)][j4]);           \
    const float4 R = *reinterpret_cast<const float4*>(&sp[(r)][j4 + 4]);       \
    hs.x = L.x + L.y + L.z + L.w + R.x;                                        \
    hs.y = hs.x - L.x + R.y;                                                   \
    hs.z = hs.y - L.y + R.z;                                                   \
    hs.w = hs.z - L.z + R.w;                                                   \
    const float qLx = L.x * L.x, qLy = L.y * L.y;                              \
    const float qLz = L.z * L.z, qLw = L.w * L.w;                              \
    const float qRx = R.x * R.x, qRy = R.y * R.y;                              \
    const float qRz = R.z * R.z, qRw = R.w * R.w;                              \
    hq.x = qLx + qLy + qLz + qLw + qRx;                                        \
    hq.y = hq.x - qLx + qRy;                                                   \
    hq.z = hq.y - qLy + qRz;                                                   \
    hq.w = hq.z - qLz + qRw;                                                   \
}

__global__ __launch_bounds__(256, 4) void k_pass1(
    const float* __restrict__ yd,
    const float* __restrict__ ygt,
    float* __restrict__ out)
{
    __shared__ __align__(16) float sp[SH2][SW3];   // 35.9 KB sigmoid tile
    __shared__ float wsum[8];

    const int img  = blockIdx.z;
    const int col0 = blockIdx.x * TW;
    const int row0 = blockIdx.y * TH;
    const float* __restrict__ yimg = yd  + (long long)img * HWLL;
    const float* __restrict__ gimg = ygt + (long long)img * HWLL;
    float* __restrict__ oimg = out + (long long)img * HWLL;

    const int tid = threadIdx.y * 32 + threadIdx.x;

    // ---- fill main body: smem cols 2..129 <- global cols col0..col0+127 ----
    // aligned float4 LDG; smem store is 8B-offset -> two float2 STS.64
    #pragma unroll 2
    for (int t = tid; t < SH2 * 32; t += 256) {
        const int li = t >> 5;
        const int v  = t & 31;
        const int gi = row0 + li - 2;
        float4 r = make_float4(0.f, 0.f, 0.f, 0.f);
        if ((unsigned)gi < (unsigned)HH) {
            float4 yv = *reinterpret_cast<const float4*>(yimg + gi * WW + col0 + v * 4);
            r.x = sigm(yv.x); r.y = sigm(yv.y); r.z = sigm(yv.z); r.w = sigm(yv.w);
        }
        *reinterpret_cast<float2*>(&sp[li][2 + v * 4]) = make_float2(r.x, r.y);
        *reinterpret_cast<float2*>(&sp[li][4 + v * 4]) = make_float2(r.z, r.w);
    }
    // ---- fill edge columns (scalar): smem cols {0,1,130,131} ----
    for (int t = tid; t < SH2 * 4; t += 256) {
        const int li = t >> 2;
        const int e  = t & 3;
        const int sc = (e < 2) ? e : (e + 128);        // 0,1,130,131
        const int gj = col0 + ((e < 2) ? (e - 2) : (e + 126)); // -2,-1,+128,+129
        const int gi = row0 + li - 2;
        float v = 0.0f;
        if ((unsigned)gi < (unsigned)HH && (unsigned)gj < (unsigned)WW)
            v = sigm(yimg[gi * WW + gj]);
        sp[li][sc] = v;
    }
    __syncthreads();

    const int j4   = threadIdx.x * 4;        // local output col base
    const int gj0  = col0 + j4;
    const int r0   = threadIdx.y * 8;        // first output row (smem offset)

    float fcx[4], rinvI[4];                  // rinvI valid for interior rows
    #pragma unroll
    for (int m = 0; m < 4; ++m) {
        const int gj = gj0 + m;
        fcx[m]   = (float)(min(gj, 2) + min(WW - 1 - gj, 2) + 1);
        rinvI[m] = __fdividef(1.0f, fcx[m] * 5.0f - 1.0f);
    }

    float4 S = make_float4(0.f, 0.f, 0.f, 0.f);
    float4 Q = make_float4(0.f, 0.f, 0.f, 0.f);
    #pragma unroll
    for (int k = 0; k < 4; ++k) {
        float4 hs, hq;
        HSQ(r0 + k, hs, hq);
        S.x += hs.x; S.y += hs.y; S.z += hs.z; S.w += hs.w;
        Q.x += hq.x; Q.y += hq.y; Q.z += hq.z; Q.w += hq.w;
    }

    float lsum = 0.0f;

    #pragma unroll
    for (int o = 0; o < 8; ++o) {
        const int gi = row0 + r0 + o;
        const float4 gv = *reinterpret_cast<const float4*>(gimg + gi * WW + gj0);

        {   // incoming window row
            float4 hs, hq;
            HSQ(r0 + o + 4, hs, hq);
            S.x += hs.x; S.y += hs.y; S.z += hs.z; S.w += hs.w;
            Q.x += hq.x; Q.y += hq.y; Q.z += hq.z; Q.w += hq.w;
        }

        // center-row p values: smem cols j4+2..j4+5 via two aligned LDS.64
        const float2 pa = *reinterpret_cast<const float2*>(&sp[r0 + o + 2][j4 + 2]);
        const float2 pb = *reinterpret_cast<const float2*>(&sp[r0 + o + 2][j4 + 4]);
        const float4 P0 = make_float4(pa.x, pa.y, pb.x, pb.y);

        const bool  yin = (gi >= 2) & (gi < HH - 2);       // warp-uniform
        const float fcy = yin ? 5.0f
                              : (float)(min(gi, 2) + min(HH - 1 - gi, 2) + 1);

        float4 w;
        #define DO_COMP(c, mi)                                                  \
        {                                                                       \
            const float fnv  = fcx[mi] * fcy;                                   \
            const float rinv = yin ? rinvI[mi]                                  \
                                   : __fdividef(1.0f, fnv - 1.0f);              \
            const float p0  = P0.c;                                             \
            const float acc = fmaf(fmaf(fnv, p0, -2.0f * S.c), p0, Q.c);        \
            const float cons = 1.0f - acc * rinv;                               \
            const float qq  = 1.0f - p0;                                        \
            const float l2p = __log2f(fmaxf(p0, 1e-37f));                       \
            const float l2q = __log2f(fmaxf(qq, 1e-37f));                       \
            const float ent = fmaf(p0, l2p, fmaf(qq, l2q, 1.0f));               \
            float ww = fmaxf(cons * ent, gv.c);                                 \
            w.c = fmaf(1.0f - MIN_WEIGHT, ww, MIN_WEIGHT);                      \
        }
        DO_COMP(x, 0)
        DO_COMP(y, 1)
        DO_COMP(z, 2)
        DO_COMP(w, 3)
        #undef DO_COMP

        *reinterpret_cast<float4*>(oimg + gi * WW + gj0) = w;
        lsum += (w.x + w.y) + (w.z + w.w);

        if (o < 7) {   // leaving window row
            float4 hs, hq;
            HSQ(r0 + o, hs, hq);
            S.x -= hs.x; S.y -= hs.y; S.z -= hs.z; S.w -= hs.w;
            Q.x -= hq.x; Q.y -= hq.y; Q.z -= hq.z; Q.w -= hq.w;
        }
    }

    // ---- block reduction -> one partial per block (no atomics) ----
    #pragma unroll
    for (int o = 16; o; o >>= 1) lsum += __shfl_down_sync(0xffffffffu, lsum, o);
    if ((tid & 31) == 0) wsum[tid >> 5] = lsum;
    __syncthreads();
    if (tid < 8) {
        float v = wsum[tid];
        #pragma unroll
        for (int o = 4; o; o >>= 1) v += __shfl_down_sync(0xffu, v, o);
        if (tid == 0)
            g_part[img * BPI + blockIdx.y * BLOCKS_X + blockIdx.x] = v;
    }
}

// in-place per-image normalization: out *= HW / sum[img]; 4 float4 per thread
__global__ __launch_bounds__(256) void k_pass2(float* __restrict__ out) {
    const int img = blockIdx.y;
    float4* p = reinterpret_cast<float4*>(out + (long long)img * HWLL);
    const int tid  = threadIdx.x;
    const int base = blockIdx.x * 1024 + tid;

    // issue data loads first so they are in flight during the reduction
    float4 a = p[base];
    float4 b = p[base + 256];
    float4 c = p[base + 512];
    float4 d = p[base + 768];

    __shared__ float s_scale;
    if (tid < 32) {
        float v = 0.0f;
        #pragma unroll
        for (int t = 0; t < 3; ++t) {
            const int idx = tid + t * 32;
            if (idx < BPI) v += g_part[img * BPI + idx];
        }
        #pragma unroll
        for (int o = 16; o; o >>= 1) v += __shfl_down_sync(0xffffffffu, v, o);
        if (tid == 0) s_scale = __fdividef((float)HWI, v);
    }
    __syncthreads();
    const float s = s_scale;

    a.x *= s; a.y *= s; a.z *= s; a.w *= s;
    b.x *= s; b.y *= s; b.z *= s; b.w *= s;
    c.x *= s; c.y *= s; c.z *= s; c.w *= s;
    d.x *= s; d.y *= s; d.z *= s; d.w *= s;
    p[base]       = a;
    p[base + 256] = b;
    p[base + 512] = c;
    p[base + 768] = d;
}

extern "C" void kernel_launch(void* const* d_in, const int* in_sizes, int n_in,
                              void* d_out, int out_size) {
    const float* yd  = (const float*)d_in[0];
    const float* ygt = (const float*)d_in[1];
    float* out = (float*)d_out;

    dim3 b1(32, 8);
    dim3 g1(BLOCKS_X, BLOCKS_Y, NIMG);      // (6, 12, 32)
    k_pass1<<<g1, b1>>>(yd, ygt, out);

    dim3 g2(HWI / 4 / 1024, NIMG);          // (144, 32)
    k_pass2<<<g2, 256>>>(out);
}

// round 9
// speedup vs baseline: 1.0676x; 1.0676x over previous
#include <cuda_runtime.h>
#include <math.h>

// Problem constants
#define HH 768
#define WW 768
#define NIMG 32
#define HWI (768 * 768)
#define HWLL (768LL * 768LL)

// Tile: 128 cols x 64 rows per block; block (32,8); thread = 4 cols x 8 rows
#define TW 128
#define TH 64
#define SW2 136              // TW + 8 (4-col halo both sides, float4 aligned)
#define SH2 68               // TH + 4
#define BLOCKS_X (WW / TW)   // 6
#define BLOCKS_Y (HH / TH)   // 12
#define BPI (BLOCKS_X * BLOCKS_Y)  // 72 blocks per image

#define MIN_WEIGHT 0.1f

__device__ float g_part[NIMG * BPI];   // fully rewritten every run

__device__ __forceinline__ float tanh_a(float x) {
    float r;
    asm("tanh.approx.f32 %0, %1;" : "=f"(r) : "f"(x));
    return r;
}
__device__ __forceinline__ float sigm(float x) {
    return fmaf(0.5f, tanh_a(0.5f * x), 0.5f);
}

// 5-wide horizontal sums for 4 outputs from three aligned float4 LDS
#define HSQ(r, hs, hq)                                                         \
{                                                                              \
    const float4 A = *reinterpret_cast<const float4*>(&sp[(r)][j4]);           \
    const float4 B = *reinterpret_cast<const float4*>(&sp[(r)][j4 + 4]);       \
    const float4 C = *reinterpret_cast<const float4*>(&sp[(r)][j4 + 8]);       \
    hs.x = A.z + A.w + B.x + B.y + B.z;                                        \
    hs.y = hs.x - A.z + B.w;                                                   \
    hs.z = hs.y - A.w + C.x;                                                   \
    hs.w = hs.z - B.x + C.y;                                                   \
    const float qAz = A.z * A.z, qAw = A.w * A.w;                              \
    const float qBx = B.x * B.x, qBy = B.y * B.y;                              \
    const float qBz = B.z * B.z, qBw = B.w * B.w;                              \
    const float qCx = C.x * C.x, qCy = C.y * C.y;                              \
    hq.x = qAz + qAw + qBx + qBy + qBz;                                        \
    hq.y = hq.x - qAz + qBw;                                                   \
    hq.z = hq.y - qAw + qCx;                                                   \
    hq.w = hq.z - qBx + qCy;                                                   \
}

__global__ __launch_bounds__(256, 4) void k_pass1(
    const float* __restrict__ yd,
    const float* __restrict__ ygt,
    float* __restrict__ out)
{
    __shared__ float sp[SH2][SW2];
    __shared__ float wsum[8];

    const int img  = blockIdx.z;
    const int col0 = blockIdx.x * TW;
    const int row0 = blockIdx.y * TH;
    const float* __restrict__ yimg = yd  + (long long)img * HWLL;
    const float* __restrict__ gimg = ygt + (long long)img * HWLL;
    float* __restrict__ oimg = out + (long long)img * HWLL;

    const int tid = threadIdx.y * 32 + threadIdx.x;

    // ---- fill p = sigmoid(y) tile (halo: 2 rows, 4 cols; OOB -> 0) ----
    #pragma unroll 3
    for (int t = tid; t < SH2 * 34; t += 256) {
        const int li = t / 34;
        const int v  = t - li * 34;
        const int gi = row0 + li - 2;
        const int gj = col0 + v * 4 - 4;
        float4 r = make_float4(0.f, 0.f, 0.f, 0.f);
        if ((unsigned)gi < (unsigned)HH && (unsigned)gj <= (unsigned)(WW - 4)) {
            float4 yv = *reinterpret_cast<const float4*>(yimg + gi * WW + gj);
            r.x = sigm(yv.x); r.y = sigm(yv.y); r.z = sigm(yv.z); r.w = sigm(yv.w);
        }
        *reinterpret_cast<float4*>(&sp[li][v * 4]) = r;
    }
    __syncthreads();

    const int j4   = threadIdx.x * 4;
    const int gj0  = col0 + j4;
    const int r0   = threadIdx.y * 8;        // first output row (smem offset)
    const int gi0  = row0 + r0;

    float fcx[4], rinvI[4];                  // rinvI valid for interior rows
    #pragma unroll
    for (int m = 0; m < 4; ++m) {
        const int gj = gj0 + m;
        fcx[m]   = (float)(min(gj, 2) + min(WW - 1 - gj, 2) + 1);
        rinvI[m] = __fdividef(1.0f, fcx[m] * 5.0f - 1.0f);
    }

    // distance-2 double-buffered prefetch of y_gt rows
    float4 gvb[2];
    gvb[0] = *reinterpret_cast<const float4*>(gimg + gi0 * WW + gj0);
    gvb[1] = *reinterpret_cast<const float4*>(gimg + (gi0 + 1) * WW + gj0);

    float4 S = make_float4(0.f, 0.f, 0.f, 0.f);
    float4 Q = make_float4(0.f, 0.f, 0.f, 0.f);
    #pragma unroll
    for (int k = 0; k < 4; ++k) {
        float4 hs, hq;
        HSQ(r0 + k, hs, hq);
        S.x += hs.x; S.y += hs.y; S.z += hs.z; S.w += hs.w;
        Q.x += hq.x; Q.y += hq.y; Q.z += hq.z; Q.w += hq.w;
    }

    float lsum = 0.0f;

    #pragma unroll
    for (int o = 0; o < 8; ++o) {
        const int gi = gi0 + o;
        const float4 gv = gvb[o & 1];
        if (o + 2 < 8)    // prefetch row o+2 into the slot just consumed
            gvb[o & 1] = *reinterpret_cast<const float4*>(gimg + (gi + 2) * WW + gj0);

        {   // incoming window row
            float4 hs, hq;
            HSQ(r0 + o + 4, hs, hq);
            S.x += hs.x; S.y += hs.y; S.z += hs.z; S.w += hs.w;
            Q.x += hq.x; Q.y += hq.y; Q.z += hq.z; Q.w += hq.w;
        }

        const float4 P0 = *reinterpret_cast<const float4*>(&sp[r0 + o + 2][j4 + 4]);

        const bool  yin = (gi >= 2) & (gi < HH - 2);       // warp-uniform
        const float fcy = yin ? 5.0f
                              : (float)(min(gi, 2) + min(HH - 1 - gi, 2) + 1);

        float4 w;
        #define DO_COMP(c, mi)                                                  \
        {                                                                       \
            const float fnv  = fcx[mi] * fcy;                                   \
            const float rinv = yin ? rinvI[mi]                                  \
                                   : __fdividef(1.0f, fnv - 1.0f);              \
            const float p0  = P0.c;                                             \
            const float acc = fmaf(fmaf(fnv, p0, -2.0f * S.c), p0, Q.c);        \
            const float cons = 1.0f - acc * rinv;                               \
            const float qq  = 1.0f - p0;                                        \
            const float l2p = __log2f(fmaxf(p0, 1e-37f));                       \
            const float l2q = __log2f(fmaxf(qq, 1e-37f));                       \
            const float ent = fmaf(p0, l2p, fmaf(qq, l2q, 1.0f));               \
            float ww = fmaxf(cons * ent, gv.c);                                 \
            w.c = fmaf(1.0f - MIN_WEIGHT, ww, MIN_WEIGHT);                      \
        }
        DO_COMP(x, 0)
        DO_COMP(y, 1)
        DO_COMP(z, 2)
        DO_COMP(w, 3)
        #undef DO_COMP

        *reinterpret_cast<float4*>(oimg + gi * WW + gj0) = w;
        lsum += (w.x + w.y) + (w.z + w.w);

        if (o < 7) {   // leaving window row
            float4 hs, hq;
            HSQ(r0 + o, hs, hq);
            S.x -= hs.x; S.y -= hs.y; S.z -= hs.z; S.w -= hs.w;
            Q.x -= hq.x; Q.y -= hq.y; Q.z -= hq.z; Q.w -= hq.w;
        }
    }

    // ---- block reduction -> one partial per block (no atomics) ----
    #pragma unroll
    for (int o = 16; o; o >>= 1) lsum += __shfl_down_sync(0xffffffffu, lsum, o);
    if ((tid & 31) == 0) wsum[tid >> 5] = lsum;
    __syncthreads();
    if (tid < 8) {
        float v = wsum[tid];
        #pragma unroll
        for (int o = 4; o; o >>= 1) v += __shfl_down_sync(0xffu, v, o);
        if (tid == 0)
            g_part[img * BPI + blockIdx.y * BLOCKS_X + blockIdx.x] = v;
    }
}

// in-place per-image normalization: out *= HW / sum[img]; 8 float4 per thread
__global__ __launch_bounds__(256) void k_pass2(float* __restrict__ out) {
    const int img = blockIdx.y;
    float4* p = reinterpret_cast<float4*>(out + (long long)img * HWLL);
    const int tid  = threadIdx.x;
    const int base = blockIdx.x * 2048 + tid;

    // issue all 8 loads first (MLP=8) so they fly during the reduction
    float4 v0 = p[base];
    float4 v1 = p[base + 256];
    float4 v2 = p[base + 512];
    float4 v3 = p[base + 768];
    float4 v4 = p[base + 1024];
    float4 v5 = p[base + 1280];
    float4 v6 = p[base + 1536];
    float4 v7 = p[base + 1792];

    __shared__ float s_scale;
    if (tid < 32) {
        float v = 0.0f;
        #pragma unroll
        for (int t = 0; t < 3; ++t) {
            const int idx = tid + t * 32;
            if (idx < BPI) v += g_part[img * BPI + idx];
        }
        #pragma unroll
        for (int o = 16; o; o >>= 1) v += __shfl_down_sync(0xffffffffu, v, o);
        if (tid == 0) s_scale = __fdividef((float)HWI, v);
    }
    __syncthreads();
    const float s = s_scale;

    #define SC(v) v.x *= s; v.y *= s; v.z *= s; v.w *= s;
    SC(v0) SC(v1) SC(v2) SC(v3) SC(v4) SC(v5) SC(v6) SC(v7)
    #undef SC
    p[base]        = v0;
    p[base + 256]  = v1;
    p[base + 512]  = v2;
    p[base + 768]  = v3;
    p[base + 1024] = v4;
    p[base + 1280] = v5;
    p[base + 1536] = v6;
    p[base + 1792] = v7;
}

extern "C" void kernel_launch(void* const* d_in, const int* in_sizes, int n_in,
                              void* d_out, int out_size) {
    const float* yd  = (const float*)d_in[0];
    const float* ygt = (const float*)d_in[1];
    float* out = (float*)d_out;

    dim3 b1(32, 8);
    dim3 g1(BLOCKS_X, BLOCKS_Y, NIMG);      // (6, 12, 32)
    k_pass1<<<g1, b1>>>(yd, ygt, out);

    dim3 g2(HWI / 4 / 2048, NIMG);          // (72, 32)
    k_pass2<<<g2, 256>>>(out);
}

// round 10
// speedup vs baseline: 1.2696x; 1.1892x over previous
#include <cuda_runtime.h>
#include <math.h>

// Problem constants
#define HH 768
#define WW 768
#define NIMG 32
#define HWI (768 * 768)
#define HWLL (768LL * 768LL)

#define TW 128                 // columns per warp strip
#define ROWS 16                // output rows per warp
#define KTOT 20                // rows loaded per warp (ROWS + 4 halo)
#define CHUNKS (HH / ROWS)     // 48 row-chunks
#define BLOCKS_X (WW / TW)     // 6
#define WPI (BLOCKS_X * CHUNKS)  // 288 warp-partials per image

#define MIN_WEIGHT 0.1f

__device__ float g_part[NIMG * WPI];   // fully rewritten every run

__device__ __forceinline__ float tanh_a(float x) {
    float r;
    asm("tanh.approx.f32 %0, %1;" : "=f"(r) : "f"(x));
    return r;
}
__device__ __forceinline__ float sigm(float x) {
    return fmaf(0.5f, tanh_a(0.5f * x), 0.5f);
}

// ---- raw loads for row (gi0 + k - 2): own float4 + edge-lane 2-col halo ----
#define LOADROW(kk, Y, H0, H1)                                                  \
{                                                                               \
    const int gr = gi0 + (kk) - 2;                                              \
    Y = make_float4(0.f, 0.f, 0.f, 0.f); H0 = 0.f; H1 = 0.f;                    \
    if ((unsigned)gr < (unsigned)HH) {                                          \
        Y = *reinterpret_cast<const float4*>(yimg + gr * WW + gj0);             \
        if (eL & hasL) {                                                        \
            float2 t = *reinterpret_cast<const float2*>(yimg + gr * WW + col0 - 2); \
            H0 = t.x; H1 = t.y;                                                 \
        }                                                                       \
        if (eR & hasR) {                                                        \
            float2 t = *reinterpret_cast<const float2*>(yimg + gr * WW + col0 + TW); \
            H0 = t.x; H1 = t.y;                                                 \
        }                                                                       \
    }                                                                           \
}

// ---- process row k: sigmoid, shuffle halo, hs/hq, ring + running S/Q ----
#define PROCROW(kk, Y, H0, H1)                                                  \
{                                                                               \
    const int gr = gi0 + (kk) - 2;                                              \
    float4 p; float lz, lw, rx, ry;                                             \
    if ((unsigned)gr < (unsigned)HH) {                                          \
        p.x = sigm(Y.x); p.y = sigm(Y.y); p.z = sigm(Y.z); p.w = sigm(Y.w);     \
        const float s0 = sigm(H0), s1 = sigm(H1);                               \
        lz = __shfl_up_sync(0xffffffffu, p.z, 1);                               \
        lw = __shfl_up_sync(0xffffffffu, p.w, 1);                               \
        rx = __shfl_down_sync(0xffffffffu, p.x, 1);                             \
        ry = __shfl_down_sync(0xffffffffu, p.y, 1);                             \
        if (eL) { lz = hasL ? s0 : 0.f; lw = hasL ? s1 : 0.f; }                 \
        if (eR) { rx = hasR ? s0 : 0.f; ry = hasR ? s1 : 0.f; }                 \
    } else {                                                                    \
        p = make_float4(0.f, 0.f, 0.f, 0.f); lz = lw = rx = ry = 0.f;           \
    }                                                                           \
    float4 hs, hq;                                                              \
    hs.x = lz + lw + p.x + p.y + p.z;                                           \
    hs.y = hs.x - lz + p.w;                                                     \
    hs.z = hs.y - lw + rx;                                                      \
    hs.w = hs.z - p.x + ry;                                                     \
    const float qlz = lz*lz, qlw = lw*lw, qx = p.x*p.x, qy = p.y*p.y;           \
    const float qz = p.z*p.z, qw = p.w*p.w, qrx = rx*rx, qry = ry*ry;           \
    hq.x = qlz + qlw + qx + qy + qz;                                            \
    hq.y = hq.x - qlz + qw;                                                     \
    hq.z = hq.y - qlw + qrx;                                                    \
    hq.w = hq.z - qx + qry;                                                     \
    S.x += hs.x - hsR[(kk) % 5].x;  S.y += hs.y - hsR[(kk) % 5].y;              \
    S.z += hs.z - hsR[(kk) % 5].z;  S.w += hs.w - hsR[(kk) % 5].w;              \
    Q.x += hq.x - hqR[(kk) % 5].x;  Q.y += hq.y - hqR[(kk) % 5].y;              \
    Q.z += hq.z - hqR[(kk) % 5].z;  Q.w += hq.w - hqR[(kk) % 5].w;              \
    hsR[(kk) % 5] = hs;  hqR[(kk) % 5] = hq;                                    \
    pR[(kk) % 3] = p;                                                           \
}

__global__ __launch_bounds__(128, 4) void k_pass1(
    const float* __restrict__ yd,
    const float* __restrict__ ygt,
    float* __restrict__ out)
{
    const int lane = threadIdx.x & 31;
    const int wrp  = threadIdx.x >> 5;
    const int img  = blockIdx.z;
    const int col0 = blockIdx.x * TW;
    const int chunk = blockIdx.y * 4 + wrp;      // 0..47
    const int gi0  = chunk * ROWS;               // first output row
    const int gj0  = col0 + lane * 4;

    const float* __restrict__ yimg = yd  + (long long)img * HWLL;
    const float* __restrict__ gimg = ygt + (long long)img * HWLL;
    float* __restrict__ oimg = out + (long long)img * HWLL;

    const bool eL = (lane == 0), eR = (lane == 31);
    const bool hasL = (col0 > 0), hasR = (col0 + TW < WW);

    float fcx[4], rinvI[4];
    #pragma unroll
    for (int m = 0; m < 4; ++m) {
        const int gj = gj0 + m;
        fcx[m]   = (float)(min(gj, 2) + min(WW - 1 - gj, 2) + 1);
        rinvI[m] = __fdividef(1.0f, fcx[m] * 5.0f - 1.0f);
    }

    float4 hsR[5], hqR[5], pR[3];
    #pragma unroll
    for (int i = 0; i < 5; ++i) {
        hsR[i] = make_float4(0.f, 0.f, 0.f, 0.f);
        hqR[i] = make_float4(0.f, 0.f, 0.f, 0.f);
    }
    float4 S = make_float4(0.f, 0.f, 0.f, 0.f);
    float4 Q = make_float4(0.f, 0.f, 0.f, 0.f);

    // y_gt distance-2 prefetch ring (rows gi0, gi0+1 always in bounds)
    float4 gvR[2];
    gvR[0] = *reinterpret_cast<const float4*>(gimg + gi0 * WW + gj0);
    gvR[1] = *reinterpret_cast<const float4*>(gimg + (gi0 + 1) * WW + gj0);

    float lsum = 0.0f;

    float4 yc, yn; float hc0, hc1, hn0, hn1;
    LOADROW(0, yc, hc0, hc1)

    #pragma unroll
    for (int k = 0; k < KTOT; ++k) {
        if (k + 1 < KTOT) { LOADROW(k + 1, yn, hn0, hn1) }

        PROCROW(k, yc, hc0, hc1)

        if (k >= 4) {
            const int o   = k - 4;
            const int gro = gi0 + o;
            const float4 gv = gvR[o & 1];
            if (o + 2 < ROWS)
                gvR[o & 1] = *reinterpret_cast<const float4*>(gimg + (gro + 2) * WW + gj0);

            const float4 P0 = pR[(k - 2) % 3];
            const bool  yin = (gro >= 2) & (gro < HH - 2);   // warp-uniform
            const float fcy = yin ? 5.0f
                                  : (float)(min(gro, 2) + min(HH - 1 - gro, 2) + 1);

            float4 w;
            #define DO_COMP(c, mi)                                              \
            {                                                                   \
                const float fnv  = fcx[mi] * fcy;                               \
                const float rinv = yin ? rinvI[mi]                              \
                                       : __fdividef(1.0f, fnv - 1.0f);          \
                const float p0  = P0.c;                                         \
                const float acc = fmaf(fmaf(fnv, p0, -2.0f * S.c), p0, Q.c);    \
                const float cons = 1.0f - acc * rinv;                           \
                const float qq  = 1.0f - p0;                                    \
                const float l2p = __log2f(fmaxf(p0, 1e-37f));                   \
                const float l2q = __log2f(fmaxf(qq, 1e-37f));                   \
                const float ent = fmaf(p0, l2p, fmaf(qq, l2q, 1.0f));           \
                float ww = fmaxf(cons * ent, gv.c);                             \
                w.c = fmaf(1.0f - MIN_WEIGHT, ww, MIN_WEIGHT);                  \
            }
            DO_COMP(x, 0)
            DO_COMP(y, 1)
            DO_COMP(z, 2)
            DO_COMP(w, 3)
            #undef DO_COMP

            *reinterpret_cast<float4*>(oimg + gro * WW + gj0) = w;
            lsum += (w.x + w.y) + (w.z + w.w);
        }

        yc = yn; hc0 = hn0; hc1 = hn1;
    }

    // ---- warp reduction -> one partial per warp (no smem, no barrier) ----
    #pragma unroll
    for (int o = 16; o; o >>= 1) lsum += __shfl_down_sync(0xffffffffu, lsum, o);
    if (lane == 0)
        g_part[img * WPI + chunk * BLOCKS_X + blockIdx.x] = lsum;
}

// in-place per-image normalization: out *= HW / sum[img]; 8 float4 per thread
__global__ __launch_bounds__(256) void k_pass2(float* __restrict__ out) {
    const int img = blockIdx.y;
    float4* p = reinterpret_cast<float4*>(out + (long long)img * HWLL);
    const int tid  = threadIdx.x;
    const int base = blockIdx.x * 2048 + tid;

    // issue all 8 loads first (MLP=8) so they fly during the reduction
    float4 v0 = p[base];
    float4 v1 = p[base + 256];
    float4 v2 = p[base + 512];
    float4 v3 = p[base + 768];
    float4 v4 = p[base + 1024];
    float4 v5 = p[base + 1280];
    float4 v6 = p[base + 1536];
    float4 v7 = p[base + 1792];

    __shared__ float s_scale;
    if (tid < 32) {
        float v = 0.0f;
        #pragma unroll
        for (int t = 0; t < 9; ++t) {
            const int idx = tid + t * 32;
            if (idx < WPI) v += g_part[img * WPI + idx];
        }
        #pragma unroll
        for (int o = 16; o; o >>= 1) v += __shfl_down_sync(0xffffffffu, v, o);
        if (tid == 0) s_scale = __fdividef((float)HWI, v);
    }
    __syncthreads();
    const float s = s_scale;

    #define SC(v) v.x *= s; v.y *= s; v.z *= s; v.w *= s;
    SC(v0) SC(v1) SC(v2) SC(v3) SC(v4) SC(v5) SC(v6) SC(v7)
    #undef SC
    p[base]        = v0;
    p[base + 256]  = v1;
    p[base + 512]  = v2;
    p[base + 768]  = v3;
    p[base + 1024] = v4;
    p[base + 1280] = v5;
    p[base + 1536] = v6;
    p[base + 1792] = v7;
}

extern "C" void kernel_launch(void* const* d_in, const int* in_sizes, int n_in,
                              void* d_out, int out_size) {
    const float* yd  = (const float*)d_in[0];
    const float* ygt = (const float*)d_in[1];
    float* out = (float*)d_out;

    dim3 b1(128);
    dim3 g1(BLOCKS_X, CHUNKS / 4, NIMG);    // (6, 12, 32) blocks of 4 warps
    k_pass1<<<g1, b1>>>(yd, ygt, out);

    dim3 g2(HWI / 4 / 2048, NIMG);          // (72, 32)
    k_pass2<<<g2, 256>>>(out);
}